// round 3
// baseline (speedup 1.0000x reference)
#include <cuda_runtime.h>
#include <cstdint>
#include <cstddef>

// Problem constants
#define NB    8
#define SS    1024
#define DIN   1280
#define RNK   64
#define DOUT  1280
#define MTOT  (NB * SS)                 // 8192
#define DOWN_SIZE (RNK * DIN)           // 81920
#define UP_SIZE   (DOUT * RNK)          // 81920
#define EMB_STRIDE (DOWN_SIZE + UP_SIZE) // 163840

// Intermediate h = x @ W_down^T : [8192, 64] fp32 (2 MB device scratch)
__device__ float g_h[MTOT * RNK];

__device__ __forceinline__ unsigned f2tf(float f) {
    unsigned u;
    asm("cvt.rna.tf32.f32 %0, %1;" : "=r"(u) : "f"(f));
    return u;
}

__device__ __forceinline__ void mma_tf32(float c[4],
                                         unsigned a0, unsigned a1, unsigned a2, unsigned a3,
                                         unsigned b0, unsigned b1) {
    asm volatile(
        "mma.sync.aligned.m16n8k8.row.col.f32.tf32.tf32.f32 "
        "{%0,%1,%2,%3}, {%4,%5,%6,%7}, {%8,%9}, {%0,%1,%2,%3};"
        : "+f"(c[0]), "+f"(c[1]), "+f"(c[2]), "+f"(c[3])
        : "r"(a0), "r"(a1), "r"(a2), "r"(a3), "r"(b0), "r"(b1));
}

// ---------------------------------------------------------------------------
// GEMM1: h[m, r] = sum_d x[m, d] * w_down[b, r, d]
//   CTA: 64 rows (m) x 64 cols (r), K tiled at 32, reg-prefetch double buffer.
//   grid = 128 (bid -> m0 = bid*64, batch = bid/16), block = 256 (8 warps).
//   Warp tile 32m x 16n: mma grid 2x2.
// ---------------------------------------------------------------------------
__global__ __launch_bounds__(256) void lora_gemm1(const float* __restrict__ x,
                                                  const float* __restrict__ embed) {
    __shared__ unsigned As[64 * 36];   // [m][k] stride 36 (36%32==4 -> conflict-free frags)
    __shared__ unsigned Bs[64 * 36];   // [r][k]

    const int tid   = threadIdx.x;
    const int bid   = blockIdx.x;
    const int m0    = bid * 64;
    const int batch = bid >> 4;        // 16 m-chunks per batch
    const float* __restrict__ wd = embed + (size_t)batch * EMB_STRIDE;

    // Tile loaders: 64 rows x 8 float4 per tile; thread covers rows lr, lr+32 at seg ls.
    const int lr = tid >> 3;           // 0..31
    const int ls = tid & 7;            // 0..7
    const float4* xg0 = reinterpret_cast<const float4*>(x)  + (size_t)(m0 + lr)      * (DIN / 4) + ls;
    const float4* xg1 = reinterpret_cast<const float4*>(x)  + (size_t)(m0 + lr + 32) * (DIN / 4) + ls;
    const float4* wg0 = reinterpret_cast<const float4*>(wd) + (size_t)(lr)           * (DIN / 4) + ls;
    const float4* wg1 = reinterpret_cast<const float4*>(wd) + (size_t)(lr + 32)      * (DIN / 4) + ls;

    const int wid  = tid >> 5;
    const int lane = tid & 31;
    const int wm = (wid & 1) * 32;     // 0 / 32
    const int wn = (wid >> 1) * 16;    // 0..48
    const int g = lane >> 2;           // 0..7
    const int t = lane & 3;            // 0..3

    float acc[2][2][4];
    #pragma unroll
    for (int mi = 0; mi < 2; mi++)
        #pragma unroll
        for (int ni = 0; ni < 2; ni++)
            #pragma unroll
            for (int j = 0; j < 4; j++) acc[mi][ni][j] = 0.f;

    // prologue prefetch (kt = 0)
    float4 ra0 = xg0[0], ra1 = xg1[0], rb0 = wg0[0], rb1 = wg1[0];

    const int NKT = DIN / 32;          // 40
    for (int kt = 0; kt < NKT; ++kt) {
        // stage current prefetch into smem (tf32-converted)
        {
            unsigned* p = &As[lr * 36 + ls * 4];
            p[0] = f2tf(ra0.x); p[1] = f2tf(ra0.y); p[2] = f2tf(ra0.z); p[3] = f2tf(ra0.w);
            p = &As[(lr + 32) * 36 + ls * 4];
            p[0] = f2tf(ra1.x); p[1] = f2tf(ra1.y); p[2] = f2tf(ra1.z); p[3] = f2tf(ra1.w);
            p = &Bs[lr * 36 + ls * 4];
            p[0] = f2tf(rb0.x); p[1] = f2tf(rb0.y); p[2] = f2tf(rb0.z); p[3] = f2tf(rb0.w);
            p = &Bs[(lr + 32) * 36 + ls * 4];
            p[0] = f2tf(rb1.x); p[1] = f2tf(rb1.y); p[2] = f2tf(rb1.z); p[3] = f2tf(rb1.w);
        }
        // prefetch next K tile while this one is being consumed
        {
            int nkt = (kt + 1 < NKT) ? (kt + 1) : kt;   // clamped (last iter re-loads harmlessly)
            ra0 = xg0[nkt * 8]; ra1 = xg1[nkt * 8];
            rb0 = wg0[nkt * 8]; rb1 = wg1[nkt * 8];
        }
        __syncthreads();

        #pragma unroll
        for (int k8 = 0; k8 < 32; k8 += 8) {
            unsigned a[2][4];
            #pragma unroll
            for (int mi = 0; mi < 2; mi++) {
                const unsigned* p = &As[(wm + mi * 16 + g) * 36 + k8 + t];
                a[mi][0] = p[0];
                a[mi][1] = p[8 * 36];
                a[mi][2] = p[4];
                a[mi][3] = p[8 * 36 + 4];
            }
            unsigned bf[2][2];
            #pragma unroll
            for (int ni = 0; ni < 2; ni++) {
                const unsigned* p = &Bs[(wn + ni * 8 + g) * 36 + k8 + t];
                bf[ni][0] = p[0];
                bf[ni][1] = p[4];
            }
            #pragma unroll
            for (int mi = 0; mi < 2; mi++)
                #pragma unroll
                for (int ni = 0; ni < 2; ni++)
                    mma_tf32(acc[mi][ni], a[mi][0], a[mi][1], a[mi][2], a[mi][3],
                             bf[ni][0], bf[ni][1]);
        }
        __syncthreads();
    }

    // epilogue: h is [MTOT][64] fp32
    #pragma unroll
    for (int mi = 0; mi < 2; mi++)
        #pragma unroll
        for (int ni = 0; ni < 2; ni++) {
            int row = m0 + wm + mi * 16 + g;
            int col = wn + ni * 8 + 2 * t;
            *reinterpret_cast<float2*>(&g_h[(size_t)row * RNK + col]) =
                make_float2(acc[mi][ni][0], acc[mi][ni][1]);
            *reinterpret_cast<float2*>(&g_h[(size_t)(row + 8) * RNK + col]) =
                make_float2(acc[mi][ni][2], acc[mi][ni][3]);
        }
}

// ---------------------------------------------------------------------------
// GEMM2: out[m, o] = sum_r h[m, r] * w_up[b, o, r]   (K = 64, single shot)
//   CTA: 64 rows (m) x 64 cols (o). grid = (128 m-chunks, 20 o-chunks).
//   Warp tile 32m x 16n.
// ---------------------------------------------------------------------------
__global__ __launch_bounds__(256) void lora_gemm2(const float* __restrict__ embed,
                                                  float* __restrict__ out) {
    __shared__ unsigned Hs[64 * 68];   // [m][k] stride 68 (68%32==4)
    __shared__ unsigned Ws[64 * 68];   // [o][k]

    const int tid   = threadIdx.x;
    const int m0    = blockIdx.x * 64;
    const int n0    = blockIdx.y * 64;
    const int batch = blockIdx.x >> 4;
    const float* __restrict__ wu = embed + (size_t)batch * EMB_STRIDE + DOWN_SIZE;

    // load tiles: 64 rows x 16 float4 each; thread -> row tid>>2, 4 consecutive float4
    {
        const int r = tid >> 2;        // 0..63
        const int s = (tid & 3) * 4;   // 0,4,8,12 (float4 units)
        const float4* hg = reinterpret_cast<const float4*>(g_h + (size_t)(m0 + r) * RNK) + s;
        unsigned* dh = &Hs[r * 68 + s * 4];
        #pragma unroll
        for (int i = 0; i < 4; i++) {
            float4 v = hg[i];
            dh[i * 4 + 0] = f2tf(v.x); dh[i * 4 + 1] = f2tf(v.y);
            dh[i * 4 + 2] = f2tf(v.z); dh[i * 4 + 3] = f2tf(v.w);
        }
        const float4* wg = reinterpret_cast<const float4*>(wu + (size_t)(n0 + r) * RNK) + s;
        unsigned* dw = &Ws[r * 68 + s * 4];
        #pragma unroll
        for (int i = 0; i < 4; i++) {
            float4 v = wg[i];
            dw[i * 4 + 0] = f2tf(v.x); dw[i * 4 + 1] = f2tf(v.y);
            dw[i * 4 + 2] = f2tf(v.z); dw[i * 4 + 3] = f2tf(v.w);
        }
    }
    __syncthreads();

    const int wid  = tid >> 5;
    const int lane = tid & 31;
    const int wm = (wid & 1) * 32;
    const int wn = (wid >> 1) * 16;
    const int g = lane >> 2;
    const int t = lane & 3;

    float acc[2][2][4];
    #pragma unroll
    for (int mi = 0; mi < 2; mi++)
        #pragma unroll
        for (int ni = 0; ni < 2; ni++)
            #pragma unroll
            for (int j = 0; j < 4; j++) acc[mi][ni][j] = 0.f;

    #pragma unroll
    for (int k8 = 0; k8 < 64; k8 += 8) {
        unsigned a[2][4];
        #pragma unroll
        for (int mi = 0; mi < 2; mi++) {
            const unsigned* p = &Hs[(wm + mi * 16 + g) * 68 + k8 + t];
            a[mi][0] = p[0];
            a[mi][1] = p[8 * 68];
            a[mi][2] = p[4];
            a[mi][3] = p[8 * 68 + 4];
        }
        unsigned bf[2][2];
        #pragma unroll
        for (int ni = 0; ni < 2; ni++) {
            const unsigned* p = &Ws[(wn + ni * 8 + g) * 68 + k8 + t];
            bf[ni][0] = p[0];
            bf[ni][1] = p[4];
        }
        #pragma unroll
        for (int mi = 0; mi < 2; mi++)
            #pragma unroll
            for (int ni = 0; ni < 2; ni++)
                mma_tf32(acc[mi][ni], a[mi][0], a[mi][1], a[mi][2], a[mi][3],
                         bf[ni][0], bf[ni][1]);
    }

    // store: out is [MTOT][1280] fp32, coalesced float2 stores
    #pragma unroll
    for (int mi = 0; mi < 2; mi++)
        #pragma unroll
        for (int ni = 0; ni < 2; ni++) {
            int row = m0 + wm + mi * 16 + g;
            int col = n0 + wn + ni * 8 + 2 * t;
            *reinterpret_cast<float2*>(&out[(size_t)row * DOUT + col]) =
                make_float2(acc[mi][ni][0], acc[mi][ni][1]);
            *reinterpret_cast<float2*>(&out[(size_t)(row + 8) * DOUT + col]) =
                make_float2(acc[mi][ni][2], acc[mi][ni][3]);
        }
}

// ---------------------------------------------------------------------------
extern "C" void kernel_launch(void* const* d_in, const int* in_sizes, int n_in,
                              void* d_out, int out_size) {
    const float* x     = (const float*)d_in[0];
    const float* embed = (const float*)d_in[1];
    // robust to input ordering: x has 10,485,760 elems, embed 1,310,720
    if (n_in >= 2 && in_sizes[0] == NB * EMB_STRIDE) {
        x     = (const float*)d_in[1];
        embed = (const float*)d_in[0];
    }
    float* out = (float*)d_out;

    lora_gemm1<<<128, 256>>>(x, embed);
    lora_gemm2<<<dim3(128, 20), 256>>>(embed, out);
}

// round 4
// speedup vs baseline: 1.4817x; 1.4817x over previous
#include <cuda_runtime.h>
#include <cstdint>
#include <cstddef>

// Problem constants
#define NB    8
#define SS    1024
#define DIN   1280
#define RNK   64
#define DOUT  1280
#define MTOT  (NB * SS)                 // 8192
#define DOWN_SIZE (RNK * DIN)           // 81920
#define UP_SIZE   (DOUT * RNK)          // 81920
#define EMB_STRIDE (DOWN_SIZE + UP_SIZE) // 163840

#define NSPLIT 4                        // split-K factor for GEMM1
#define KT_PER_SPLIT (DIN / 32 / NSPLIT) // 10

// Scratch: split-K partials (8 MB) + reduced h (2 MB)
__device__ float g_hp[NSPLIT * MTOT * RNK];
__device__ float g_h[MTOT * RNK];

__device__ __forceinline__ unsigned f2tf(float f) {
    unsigned u;
    asm("cvt.rna.tf32.f32 %0, %1;" : "=r"(u) : "f"(f));
    return u;
}

__device__ __forceinline__ uint4 f4totf(float4 v) {
    uint4 u;
    u.x = f2tf(v.x); u.y = f2tf(v.y); u.z = f2tf(v.z); u.w = f2tf(v.w);
    return u;
}

__device__ __forceinline__ void mma_tf32(float c[4],
                                         unsigned a0, unsigned a1, unsigned a2, unsigned a3,
                                         unsigned b0, unsigned b1) {
    asm volatile(
        "mma.sync.aligned.m16n8k8.row.col.f32.tf32.tf32.f32 "
        "{%0,%1,%2,%3}, {%4,%5,%6,%7}, {%8,%9}, {%0,%1,%2,%3};"
        : "+f"(c[0]), "+f"(c[1]), "+f"(c[2]), "+f"(c[3])
        : "r"(a0), "r"(a1), "r"(a2), "r"(a3), "r"(b0), "r"(b1));
}

// ---------------------------------------------------------------------------
// GEMM1 (split-K): partial h[m, r] over one K chunk of 320.
//   grid = (128, NSPLIT). CTA: 64m x 64r, K tiled at 32, reg double buffer.
//   8 warps, warp tile 32m x 16n.
// ---------------------------------------------------------------------------
__global__ __launch_bounds__(256) void lora_gemm1(const float* __restrict__ x,
                                                  const float* __restrict__ embed) {
    __shared__ unsigned S[2 * 64 * 36];
    unsigned* As = S;                 // [m][k] stride 36
    unsigned* Bs = S + 64 * 36;       // [r][k] stride 36

    const int tid   = threadIdx.x;
    const int m0    = blockIdx.x * 64;
    const int split = blockIdx.y;
    const int batch = blockIdx.x >> 4;
    const float* __restrict__ wd = embed + (size_t)batch * EMB_STRIDE;

    // loader: thread covers rows lr, lr+32 at float4 segment ls
    const int lr = tid >> 3;           // 0..31
    const int ls = tid & 7;            // 0..7
    const float4* xg0 = reinterpret_cast<const float4*>(x)  + (size_t)(m0 + lr)      * (DIN / 4) + ls;
    const float4* xg1 = reinterpret_cast<const float4*>(x)  + (size_t)(m0 + lr + 32) * (DIN / 4) + ls;
    const float4* wg0 = reinterpret_cast<const float4*>(wd) + (size_t)(lr)           * (DIN / 4) + ls;
    const float4* wg1 = reinterpret_cast<const float4*>(wd) + (size_t)(lr + 32)      * (DIN / 4) + ls;

    const int wid  = tid >> 5;
    const int lane = tid & 31;
    const int wm = (wid & 1) * 32;
    const int wn = (wid >> 1) * 16;
    const int g = lane >> 2;
    const int t = lane & 3;

    float acc[2][2][4];
    #pragma unroll
    for (int mi = 0; mi < 2; mi++)
        #pragma unroll
        for (int ni = 0; ni < 2; ni++)
            #pragma unroll
            for (int j = 0; j < 4; j++) acc[mi][ni][j] = 0.f;

    const int kt0   = split * KT_PER_SPLIT;
    const int ktend = kt0 + KT_PER_SPLIT;

    // prologue prefetch
    float4 ra0 = xg0[kt0 * 8], ra1 = xg1[kt0 * 8];
    float4 rb0 = wg0[kt0 * 8], rb1 = wg1[kt0 * 8];

    for (int kt = kt0; kt < ktend; ++kt) {
        // stage prefetched tile (packed STS.128, conflict-free)
        *reinterpret_cast<uint4*>(&As[lr * 36 + ls * 4])        = f4totf(ra0);
        *reinterpret_cast<uint4*>(&As[(lr + 32) * 36 + ls * 4]) = f4totf(ra1);
        *reinterpret_cast<uint4*>(&Bs[lr * 36 + ls * 4])        = f4totf(rb0);
        *reinterpret_cast<uint4*>(&Bs[(lr + 32) * 36 + ls * 4]) = f4totf(rb1);
        {
            int nkt = (kt + 1 < ktend) ? (kt + 1) : kt;
            ra0 = xg0[nkt * 8]; ra1 = xg1[nkt * 8];
            rb0 = wg0[nkt * 8]; rb1 = wg1[nkt * 8];
        }
        __syncthreads();

        #pragma unroll
        for (int k8 = 0; k8 < 32; k8 += 8) {
            unsigned a[2][4];
            #pragma unroll
            for (int mi = 0; mi < 2; mi++) {
                const unsigned* p = &As[(wm + mi * 16 + g) * 36 + k8 + t];
                a[mi][0] = p[0];
                a[mi][1] = p[8 * 36];
                a[mi][2] = p[4];
                a[mi][3] = p[8 * 36 + 4];
            }
            unsigned bf[2][2];
            #pragma unroll
            for (int ni = 0; ni < 2; ni++) {
                const unsigned* p = &Bs[(wn + ni * 8 + g) * 36 + k8 + t];
                bf[ni][0] = p[0];
                bf[ni][1] = p[4];
            }
            #pragma unroll
            for (int mi = 0; mi < 2; mi++)
                #pragma unroll
                for (int ni = 0; ni < 2; ni++)
                    mma_tf32(acc[mi][ni], a[mi][0], a[mi][1], a[mi][2], a[mi][3],
                             bf[ni][0], bf[ni][1]);
        }
        __syncthreads();
    }

    // ---- staged epilogue: fragments -> smem -> coalesced float4 stores ----
    float* outs = reinterpret_cast<float*>(S);   // [64][68] floats (4352 <= 4608 words)
    #pragma unroll
    for (int mi = 0; mi < 2; mi++)
        #pragma unroll
        for (int ni = 0; ni < 2; ni++) {
            int row = wm + mi * 16 + g;
            int col = wn + ni * 8 + 2 * t;
            *reinterpret_cast<float2*>(&outs[row * 68 + col]) =
                make_float2(acc[mi][ni][0], acc[mi][ni][1]);
            *reinterpret_cast<float2*>(&outs[(row + 8) * 68 + col]) =
                make_float2(acc[mi][ni][2], acc[mi][ni][3]);
        }
    __syncthreads();

    float* dst = g_hp + (size_t)split * (MTOT * RNK);
    #pragma unroll
    for (int j = 0; j < 4; j++) {
        int idx = tid + j * 256;               // 0..1023 over 64 rows x 16 float4
        int row = idx >> 4;
        int seg = idx & 15;
        float4 v = *reinterpret_cast<const float4*>(&outs[row * 68 + seg * 4]);
        *reinterpret_cast<float4*>(&dst[(size_t)(m0 + row) * RNK + seg * 4]) = v;
    }
}

// ---------------------------------------------------------------------------
// Reduce split-K partials: g_h = sum_s g_hp[s]
// ---------------------------------------------------------------------------
__global__ __launch_bounds__(256) void lora_reduce() {
    int idx = blockIdx.x * 256 + threadIdx.x;    // over MTOT*RNK/4 = 131072 float4
    const float4* p = reinterpret_cast<const float4*>(g_hp);
    const int n4 = MTOT * RNK / 4;
    float4 a = p[idx];
    float4 b = p[idx + n4];
    float4 c = p[idx + 2 * n4];
    float4 d = p[idx + 3 * n4];
    float4 r;
    r.x = (a.x + b.x) + (c.x + d.x);
    r.y = (a.y + b.y) + (c.y + d.y);
    r.z = (a.z + b.z) + (c.z + d.z);
    r.w = (a.w + b.w) + (c.w + d.w);
    reinterpret_cast<float4*>(g_h)[idx] = r;
}

// ---------------------------------------------------------------------------
// GEMM2: out[m, o] = sum_r h[m, r] * w_up[b, o, r]   (K = 64, single shot)
//   CTA tile 64m x 128o. 8 warps, warp tile 32m x 32o (mma grid 2x4).
//   grid = (128 m-chunks, 10 o-chunks). Dynamic smem = (64+128)*68*4 = 52224 B.
// ---------------------------------------------------------------------------
__global__ __launch_bounds__(256) void lora_gemm2(const float* __restrict__ embed,
                                                  float* __restrict__ out) {
    extern __shared__ unsigned smemd[];
    unsigned* Hs = smemd;              // [64][68]
    unsigned* Ws = smemd + 64 * 68;    // [128][68]

    const int tid   = threadIdx.x;
    const int m0    = blockIdx.x * 64;
    const int n0    = blockIdx.y * 128;
    const int batch = blockIdx.x >> 4;
    const float* __restrict__ wu = embed + (size_t)batch * EMB_STRIDE + DOWN_SIZE;

    // H fill: 64 rows x 16 float4, flat index, packed STS.128 (conflict-free)
    #pragma unroll
    for (int j = 0; j < 4; j++) {
        int idx = tid + j * 256;
        int row = idx >> 4;
        int seg = idx & 15;
        float4 v = reinterpret_cast<const float4*>(g_h + (size_t)(m0 + row) * RNK)[seg];
        *reinterpret_cast<uint4*>(&Hs[row * 68 + seg * 4]) = f4totf(v);
    }
    // W fill: 128 rows x 16 float4
    #pragma unroll
    for (int j = 0; j < 8; j++) {
        int idx = tid + j * 256;
        int row = idx >> 4;
        int seg = idx & 15;
        float4 v = reinterpret_cast<const float4*>(wu + (size_t)(n0 + row) * RNK)[seg];
        *reinterpret_cast<uint4*>(&Ws[row * 68 + seg * 4]) = f4totf(v);
    }
    __syncthreads();

    const int wid  = tid >> 5;
    const int lane = tid & 31;
    const int wm = (wid & 1) * 32;     // 0 / 32
    const int wn = (wid >> 1) * 32;    // 0 / 32 / 64 / 96
    const int g = lane >> 2;
    const int t = lane & 3;

    float acc[2][4][4];
    #pragma unroll
    for (int mi = 0; mi < 2; mi++)
        #pragma unroll
        for (int ni = 0; ni < 4; ni++)
            #pragma unroll
            for (int j = 0; j < 4; j++) acc[mi][ni][j] = 0.f;

    #pragma unroll
    for (int k8 = 0; k8 < 64; k8 += 8) {
        unsigned a[2][4];
        #pragma unroll
        for (int mi = 0; mi < 2; mi++) {
            const unsigned* p = &Hs[(wm + mi * 16 + g) * 68 + k8 + t];
            a[mi][0] = p[0];
            a[mi][1] = p[8 * 68];
            a[mi][2] = p[4];
            a[mi][3] = p[8 * 68 + 4];
        }
        unsigned bf[4][2];
        #pragma unroll
        for (int ni = 0; ni < 4; ni++) {
            const unsigned* p = &Ws[(wn + ni * 8 + g) * 68 + k8 + t];
            bf[ni][0] = p[0];
            bf[ni][1] = p[4];
        }
        #pragma unroll
        for (int mi = 0; mi < 2; mi++)
            #pragma unroll
            for (int ni = 0; ni < 4; ni++)
                mma_tf32(acc[mi][ni], a[mi][0], a[mi][1], a[mi][2], a[mi][3],
                         bf[ni][0], bf[ni][1]);
    }

    // ---- staged epilogue: smem transpose-gather, then coalesced STG.128 ----
    __syncthreads();
    float* outs = reinterpret_cast<float*>(smemd);   // [64][132] floats (8448 <= 13056)
    #pragma unroll
    for (int mi = 0; mi < 2; mi++)
        #pragma unroll
        for (int ni = 0; ni < 4; ni++) {
            int row = wm + mi * 16 + g;
            int col = wn + ni * 8 + 2 * t;
            *reinterpret_cast<float2*>(&outs[row * 132 + col]) =
                make_float2(acc[mi][ni][0], acc[mi][ni][1]);
            *reinterpret_cast<float2*>(&outs[(row + 8) * 132 + col]) =
                make_float2(acc[mi][ni][2], acc[mi][ni][3]);
        }
    __syncthreads();

    #pragma unroll
    for (int j = 0; j < 8; j++) {
        int idx = tid + j * 256;               // over 64 rows x 32 float4
        int row = idx >> 5;
        int seg = idx & 31;
        float4 v = *reinterpret_cast<const float4*>(&outs[row * 132 + seg * 4]);
        *reinterpret_cast<float4*>(&out[(size_t)(m0 + row) * DOUT + n0 + seg * 4]) = v;
    }
}

// ---------------------------------------------------------------------------
extern "C" void kernel_launch(void* const* d_in, const int* in_sizes, int n_in,
                              void* d_out, int out_size) {
    const float* x     = (const float*)d_in[0];
    const float* embed = (const float*)d_in[1];
    if (n_in >= 2 && in_sizes[0] == NB * EMB_STRIDE) {
        x     = (const float*)d_in[1];
        embed = (const float*)d_in[0];
    }
    float* out = (float*)d_out;

    const int smem2 = (64 + 128) * 68 * 4;   // 52224 B > 48KB static limit
    cudaFuncSetAttribute(lora_gemm2, cudaFuncAttributeMaxDynamicSharedMemorySize, smem2);

    lora_gemm1<<<dim3(128, NSPLIT), 256>>>(x, embed);
    lora_reduce<<<MTOT * RNK / 4 / 256, 256>>>();
    lora_gemm2<<<dim3(128, 10), 256, smem2>>>(embed, out);
}

// round 5
// speedup vs baseline: 1.6656x; 1.1241x over previous
#include <cuda_runtime.h>
#include <cstdint>
#include <cstddef>

// Problem constants
#define NB    8
#define SS    1024
#define DIN   1280
#define RNK   64
#define DOUT  1280
#define MTOT  (NB * SS)                  // 8192
#define DOWN_SIZE (RNK * DIN)            // 81920
#define UP_SIZE   (DOUT * RNK)           // 81920
#define EMB_STRIDE (DOWN_SIZE + UP_SIZE) // 163840

#define NSPLIT 8
#define KT_PER_SPLIT (DIN / 32 / NSPLIT) // 5

#define M16   (MTOT / 16)                // 512 m16-blocks
#define HQ_N  (M16 * 8 * 32)             // 131072 uint4 slots (h fragments)
#define WDP_N (NB * 80 * 8 * 32)         // 163840 uint4 (W_down fragments)
#define WUP_N (NB * 160 * 4 * 32)        // 163840 uint4 (W_up fragments)

// Device scratch (static — no allocation)
__device__ float4 g_hp4[NSPLIT * HQ_N];  // split-K partials, fragment order, fp32
__device__ uint4  g_hq[HQ_N];            // reduced h, tf32, A-fragment packed
__device__ uint4  g_wdp[WDP_N];          // W_down, tf32, B-fragment packed
__device__ uint4  g_wup[WUP_N];          // W_up,   tf32, B-fragment packed

__device__ __forceinline__ unsigned f2tf(float f) {
    unsigned u;
    asm("cvt.rna.tf32.f32 %0, %1;" : "=r"(u) : "f"(f));
    return u;
}

__device__ __forceinline__ uint4 f4totf(float4 v) {
    uint4 u;
    u.x = f2tf(v.x); u.y = f2tf(v.y); u.z = f2tf(v.z); u.w = f2tf(v.w);
    return u;
}

__device__ __forceinline__ void mma_tf32(float c[4],
                                         unsigned a0, unsigned a1, unsigned a2, unsigned a3,
                                         unsigned b0, unsigned b1) {
    asm volatile(
        "mma.sync.aligned.m16n8k8.row.col.f32.tf32.tf32.f32 "
        "{%0,%1,%2,%3}, {%4,%5,%6,%7}, {%8,%9}, {%0,%1,%2,%3};"
        : "+f"(c[0]), "+f"(c[1]), "+f"(c[2]), "+f"(c[3])
        : "r"(a0), "r"(a1), "r"(a2), "r"(a3), "r"(b0), "r"(b1));
}

// ---------------------------------------------------------------------------
// Prepack: embed -> tf32 fragment-packed W_down / W_up.
//   B-fragment (m16n8k8, col-major B): lane (g,t) holds (k8*8+t, n8*8+g) and
//   (k8*8+t+4, ...). Pack two k8-steps per uint4:
//     {b(k8e)0, b(k8e)1, b(k8o)0, b(k8o)1},  k8e=2*k16, k8o=2*k16+1.
//   g_wdp index: ((b*80 + k16)*8 + n8)*32 + lane      (k over d_in: 80 k16)
//   g_wup index: ((b*160 + n8)*4 + k16)*32 + lane     (k over rank: 4 k16)
// ---------------------------------------------------------------------------
__global__ __launch_bounds__(256) void lora_prepack(const float* __restrict__ embed) {
    int i = blockIdx.x * 256 + threadIdx.x;
    int lane = i & 31;
    int g = lane >> 2, t = lane & 3;
    if (i < WDP_N) {
        int r = i >> 5;
        int n8  = r & 7;  r >>= 3;
        int k16 = r % 80;
        int b   = r / 80;
        const float* W = embed + (size_t)b * EMB_STRIDE
                       + (size_t)(n8 * 8 + g) * DIN + k16 * 16;
        uint4 o;
        o.x = f2tf(W[t]); o.y = f2tf(W[t + 4]);
        o.z = f2tf(W[8 + t]); o.w = f2tf(W[12 + t]);
        g_wdp[i] = o;
    } else {
        int j = i - WDP_N;
        int r = j >> 5;
        int k16 = r & 3;  r >>= 2;
        int n8  = r % 160;
        int b   = r / 160;
        const float* W = embed + (size_t)b * EMB_STRIDE + DOWN_SIZE
                       + (size_t)(n8 * 8 + g) * RNK + k16 * 16;
        uint4 o;
        o.x = f2tf(W[t]); o.y = f2tf(W[t + 4]);
        o.z = f2tf(W[8 + t]); o.w = f2tf(W[12 + t]);
        g_wup[j] = o;
    }
}

// ---------------------------------------------------------------------------
// GEMM1 (split-K=8): partial h[m,r] over K chunk of 160.
//   grid (128, 8), 256 thr (8 warps, warp tile 32m x 16n).
//   A (x tile): smem double buffer, ONE syncthreads per kt.
//   B (W_down): fragment LDG.128 from g_wdp (L2-hot), no smem.
//   Epilogue: stage to smem, emit partials in A-fragment order (fp32).
// ---------------------------------------------------------------------------
__global__ __launch_bounds__(256, 4) void lora_gemm1(const float* __restrict__ x) {
    __shared__ unsigned As[2][64 * 36];   // stride 36 (4g+t banks conflict-free)

    const int tid   = threadIdx.x;
    const int m0    = blockIdx.x * 64;
    const int split = blockIdx.y;
    const int batch = blockIdx.x >> 4;

    const int lr = tid >> 3;           // 0..31
    const int ls = tid & 7;            // 0..7
    const float4* xg0 = reinterpret_cast<const float4*>(x) + (size_t)(m0 + lr)      * (DIN / 4) + ls;
    const float4* xg1 = reinterpret_cast<const float4*>(x) + (size_t)(m0 + lr + 32) * (DIN / 4) + ls;

    const int wid  = tid >> 5;
    const int lane = tid & 31;
    const int wm = (wid & 1) * 32;
    const int wn = (wid >> 1) * 16;
    const int g = lane >> 2;
    const int t = lane & 3;

    const uint4* __restrict__ wb = g_wdp + (size_t)batch * (80 * 8 * 32);
    const int n8b = wn >> 3;

    float acc[2][2][4];
    #pragma unroll
    for (int mi = 0; mi < 2; mi++)
        #pragma unroll
        for (int ni = 0; ni < 2; ni++)
            #pragma unroll
            for (int j = 0; j < 4; j++) acc[mi][ni][j] = 0.f;

    const int kt0   = split * KT_PER_SPLIT;
    const int ktend = kt0 + KT_PER_SPLIT;

    float4 ra0 = xg0[kt0 * 8], ra1 = xg1[kt0 * 8];

    for (int kt = kt0; kt < ktend; ++kt) {
        const int p = kt & 1;

        // B fragments for this K-tile: k16 = 2kt, 2kt+1 ; n8 = n8b, n8b+1
        uint4 bu[2][2];
        #pragma unroll
        for (int j = 0; j < 2; j++)
            #pragma unroll
            for (int ni = 0; ni < 2; ni++)
                bu[j][ni] = wb[(((2 * kt + j) * 8 + n8b + ni) << 5) + lane];

        // stage A tile (tf32-converted) into buffer p
        *reinterpret_cast<uint4*>(&As[p][lr * 36 + ls * 4])        = f4totf(ra0);
        *reinterpret_cast<uint4*>(&As[p][(lr + 32) * 36 + ls * 4]) = f4totf(ra1);

        // prefetch next A tile
        {
            int nkt = (kt + 1 < ktend) ? (kt + 1) : kt;
            ra0 = xg0[nkt * 8]; ra1 = xg1[nkt * 8];
        }
        __syncthreads();   // single barrier per kt (double buffer)

        #pragma unroll
        for (int j = 0; j < 2; j++) {
            #pragma unroll
            for (int h = 0; h < 2; h++) {
                const int k8l = 2 * j + h;
                unsigned a[2][4];
                #pragma unroll
                for (int mi = 0; mi < 2; mi++) {
                    const unsigned* pp = &As[p][(wm + mi * 16 + g) * 36 + k8l * 8 + t];
                    a[mi][0] = pp[0];
                    a[mi][1] = pp[8 * 36];
                    a[mi][2] = pp[4];
                    a[mi][3] = pp[8 * 36 + 4];
                }
                #pragma unroll
                for (int mi = 0; mi < 2; mi++)
                    #pragma unroll
                    for (int ni = 0; ni < 2; ni++) {
                        unsigned b0 = h ? bu[j][ni].z : bu[j][ni].x;
                        unsigned b1 = h ? bu[j][ni].w : bu[j][ni].y;
                        mma_tf32(acc[mi][ni], a[mi][0], a[mi][1], a[mi][2], a[mi][3], b0, b1);
                    }
            }
        }
    }

    // ---- epilogue: stage to smem, write partials in A-fragment order ----
    __syncthreads();
    float* s = reinterpret_cast<float*>(As);   // 64*68 = 4352 <= 4608 words
    #pragma unroll
    for (int mi = 0; mi < 2; mi++)
        #pragma unroll
        for (int ni = 0; ni < 2; ni++) {
            int row = wm + mi * 16 + g;
            int col = wn + ni * 8 + 2 * t;
            *reinterpret_cast<float2*>(&s[row * 68 + col]) =
                make_float2(acc[mi][ni][0], acc[mi][ni][1]);
            *reinterpret_cast<float2*>(&s[(row + 8) * 68 + col]) =
                make_float2(acc[mi][ni][2], acc[mi][ni][3]);
        }
    __syncthreads();

    float4* dst = g_hp4 + (size_t)split * HQ_N + (size_t)(m0 >> 4) * 256;
    #pragma unroll
    for (int jj = 0; jj < 4; jj++) {
        int idx = tid + jj * 256;              // 0..1023 = (ml, k8, lane)
        int ln  = idx & 31;
        int k8  = (idx >> 5) & 7;
        int ml  = idx >> 8;
        int gg = ln >> 2, tt = ln & 3;
        const float* r0 = &s[(ml * 16 + gg) * 68 + k8 * 8 + tt];
        const float* r1 = r0 + 8 * 68;
        // A-fragment order: (g,t),(g+8,t),(g,t+4),(g+8,t+4)
        dst[idx] = make_float4(r0[0], r1[0], r0[4], r1[4]);
    }
}

// ---------------------------------------------------------------------------
// Reduce: g_hq = cvt_tf32( sum over splits of g_hp4 ). Elementwise, coalesced.
// ---------------------------------------------------------------------------
__global__ __launch_bounds__(256) void lora_reduce() {
    int i = blockIdx.x * 256 + threadIdx.x;    // < HQ_N (grid 512)
    float4 sv = g_hp4[i];
    #pragma unroll
    for (int sp = 1; sp < NSPLIT; sp++) {
        float4 v = g_hp4[(size_t)sp * HQ_N + i];
        sv.x += v.x; sv.y += v.y; sv.z += v.z; sv.w += v.w;
    }
    uint4 o;
    o.x = f2tf(sv.x); o.y = f2tf(sv.y); o.z = f2tf(sv.z); o.w = f2tf(sv.w);
    g_hq[i] = o;
}

// ---------------------------------------------------------------------------
// GEMM2: out[m,o] = h[m,:] @ W_up[b]^T, K=64.
//   grid (128, 20), 256 thr (8 warps, warp tile 32m x 16n, CTA 64x64).
//   NO operand smem: A fragments LDG.128 from g_hq, B from g_wup.
//   Epilogue: staged smem -> coalesced float4 stores.
// ---------------------------------------------------------------------------
__global__ __launch_bounds__(256) void lora_gemm2(float* __restrict__ out) {
    __shared__ float s[64 * 68];

    const int tid   = threadIdx.x;
    const int m0    = blockIdx.x * 64;
    const int n0    = blockIdx.y * 64;
    const int batch = blockIdx.x >> 4;

    const int wid  = tid >> 5;
    const int lane = tid & 31;
    const int wm = (wid & 1) * 32;
    const int wn = (wid >> 1) * 16;
    const int g = lane >> 2;
    const int t = lane & 3;

    const size_t mbase = (size_t)(m0 >> 4) + (wm >> 4);          // m16 index
    const uint4* __restrict__ Ab = g_hq + mbase * 256 + lane;    // +mi*256, +k8*32
    const size_t n8b = (size_t)batch * 160 + blockIdx.y * 8 + (wn >> 3);
    const uint4* __restrict__ Bb = g_wup + n8b * 128 + lane;     // +ni*128, +k16*32

    float acc[2][2][4];
    #pragma unroll
    for (int mi = 0; mi < 2; mi++)
        #pragma unroll
        for (int ni = 0; ni < 2; ni++)
            #pragma unroll
            for (int j = 0; j < 4; j++) acc[mi][ni][j] = 0.f;

    #pragma unroll
    for (int k16 = 0; k16 < 4; k16++) {
        uint4 alo[2], ahi[2], bu[2];
        #pragma unroll
        for (int mi = 0; mi < 2; mi++) {
            alo[mi] = Ab[mi * 256 + (2 * k16) * 32];
            ahi[mi] = Ab[mi * 256 + (2 * k16 + 1) * 32];
        }
        #pragma unroll
        for (int ni = 0; ni < 2; ni++)
            bu[ni] = Bb[ni * 128 + k16 * 32];

        #pragma unroll
        for (int mi = 0; mi < 2; mi++)
            #pragma unroll
            for (int ni = 0; ni < 2; ni++) {
                mma_tf32(acc[mi][ni], alo[mi].x, alo[mi].y, alo[mi].z, alo[mi].w,
                         bu[ni].x, bu[ni].y);
                mma_tf32(acc[mi][ni], ahi[mi].x, ahi[mi].y, ahi[mi].z, ahi[mi].w,
                         bu[ni].z, bu[ni].w);
            }
    }

    // ---- staged epilogue ----
    #pragma unroll
    for (int mi = 0; mi < 2; mi++)
        #pragma unroll
        for (int ni = 0; ni < 2; ni++) {
            int row = wm + mi * 16 + g;
            int col = wn + ni * 8 + 2 * t;
            *reinterpret_cast<float2*>(&s[row * 68 + col]) =
                make_float2(acc[mi][ni][0], acc[mi][ni][1]);
            *reinterpret_cast<float2*>(&s[(row + 8) * 68 + col]) =
                make_float2(acc[mi][ni][2], acc[mi][ni][3]);
        }
    __syncthreads();

    #pragma unroll
    for (int j = 0; j < 4; j++) {
        int idx = tid + j * 256;               // 64 rows x 16 float4
        int row = idx >> 4;
        int seg = idx & 15;
        float4 v = *reinterpret_cast<const float4*>(&s[row * 68 + seg * 4]);
        *reinterpret_cast<float4*>(&out[(size_t)(m0 + row) * DOUT + n0 + seg * 4]) = v;
    }
}

// ---------------------------------------------------------------------------
extern "C" void kernel_launch(void* const* d_in, const int* in_sizes, int n_in,
                              void* d_out, int out_size) {
    const float* x     = (const float*)d_in[0];
    const float* embed = (const float*)d_in[1];
    if (n_in >= 2 && in_sizes[0] == NB * EMB_STRIDE) {
        x     = (const float*)d_in[1];
        embed = (const float*)d_in[0];
    }
    float* out = (float*)d_out;

    lora_prepack<<<(WDP_N + WUP_N) / 256, 256>>>(embed);
    lora_gemm1<<<dim3(128, NSPLIT), 256>>>(x);
    lora_reduce<<<HQ_N / 256, 256>>>();
    lora_gemm2<<<dim3(128, 20), 256>>>(out);
}

// round 6
// speedup vs baseline: 2.1204x; 1.2730x over previous
#include <cuda_runtime.h>
#include <cstdint>
#include <cstddef>

// Problem constants
#define NB    8
#define SS    1024
#define DIN   1280
#define RNK   64
#define DOUT  1280
#define MTOT  (NB * SS)                  // 8192
#define DOWN_SIZE (RNK * DIN)            // 81920
#define UP_SIZE   (DOUT * RNK)           // 81920
#define EMB_STRIDE (DOWN_SIZE + UP_SIZE) // 163840

#define NSPLIT 8
#define KT_PER_SPLIT (DIN / 32 / NSPLIT) // 5

#define M16   (MTOT / 16)                // 512 m16-blocks
#define HQ_N  (M16 * 8 * 32)             // 131072 uint4 slots (h fragments)
#define WDP_N (NB * 80 * 8 * 32)         // 163840 uint4 (W_down fragments)
#define WUP_N (NB * 160 * 4 * 32)        // 163840 uint4 (W_up fragments)

// Device scratch (static — no allocation)
__device__ float4 g_hp4[NSPLIT * HQ_N];  // split-K partials, fragment order, fp32
__device__ uint4  g_hq[HQ_N];            // reduced h, tf32, A-fragment packed
__device__ uint4  g_wdp[WDP_N];          // W_down, tf32, B-fragment packed
__device__ uint4  g_wup[WUP_N];          // W_up,   tf32, B-fragment packed

__device__ __forceinline__ unsigned f2tf(float f) {
    unsigned u;
    asm("cvt.rna.tf32.f32 %0, %1;" : "=r"(u) : "f"(f));
    return u;
}

__device__ __forceinline__ uint4 f4totf(float4 v) {
    uint4 u;
    u.x = f2tf(v.x); u.y = f2tf(v.y); u.z = f2tf(v.z); u.w = f2tf(v.w);
    return u;
}

__device__ __forceinline__ void mma_tf32(float c[4],
                                         unsigned a0, unsigned a1, unsigned a2, unsigned a3,
                                         unsigned b0, unsigned b1) {
    asm volatile(
        "mma.sync.aligned.m16n8k8.row.col.f32.tf32.tf32.f32 "
        "{%0,%1,%2,%3}, {%4,%5,%6,%7}, {%8,%9}, {%0,%1,%2,%3};"
        : "+f"(c[0]), "+f"(c[1]), "+f"(c[2]), "+f"(c[3])
        : "r"(a0), "r"(a1), "r"(a2), "r"(a3), "r"(b0), "r"(b1));
}

// ---------------------------------------------------------------------------
// Prepack: embed -> tf32 fragment-packed W_down / W_up.
//   B-fragment (m16n8k8, col-major B): lane(g,t) holds (k=t,n=g),(k=t+4,n=g);
//   two k8 steps packed per uint4: {b(k8e)0, b(k8e)1, b(k8o)0, b(k8o)1}.
//   g_wdp index: ((b*80 + k16)*8 + n8)*32 + lane      (k over d_in: 80 k16)
//   g_wup index: ((b*160 + n8)*4 + k16)*32 + lane     (k over rank: 4 k16)
// ---------------------------------------------------------------------------
__global__ __launch_bounds__(256) void lora_prepack(const float* __restrict__ embed) {
    int i = blockIdx.x * 256 + threadIdx.x;
    int lane = i & 31;
    int g = lane >> 2, t = lane & 3;
    if (i < WDP_N) {
        int r = i >> 5;
        int n8  = r & 7;  r >>= 3;
        int k16 = r % 80;
        int b   = r / 80;
        const float* W = embed + (size_t)b * EMB_STRIDE
                       + (size_t)(n8 * 8 + g) * DIN + k16 * 16;
        uint4 o;
        o.x = f2tf(W[t]); o.y = f2tf(W[t + 4]);
        o.z = f2tf(W[8 + t]); o.w = f2tf(W[12 + t]);
        g_wdp[i] = o;
    } else {
        int j = i - WDP_N;
        int r = j >> 5;
        int k16 = r & 3;  r >>= 2;
        int n8  = r % 160;
        int b   = r / 160;
        const float* W = embed + (size_t)b * EMB_STRIDE + DOWN_SIZE
                       + (size_t)(n8 * 8 + g) * RNK + k16 * 16;
        uint4 o;
        o.x = f2tf(W[t]); o.y = f2tf(W[t + 4]);
        o.z = f2tf(W[8 + t]); o.w = f2tf(W[12 + t]);
        g_wup[j] = o;
    }
}

// ---------------------------------------------------------------------------
// GEMM1 (split-K=8): partial h[m,r] over one K chunk of 160.
//   grid (128, 8), block 128 (4 warps as 2m x 2n, warp tile 32m x 32n).
//   A (x): smem double buffer, ONE syncthreads per kt.
//   B (W_down): fragment LDG from g_wdp (L2-hot).
//   Epilogue: stage to smem, emit partials in A-fragment order (fp32).
// ---------------------------------------------------------------------------
__global__ __launch_bounds__(128) void lora_gemm1(const float* __restrict__ x) {
    __shared__ unsigned As[2][64 * 36];   // 18 KB

    const int tid   = threadIdx.x;
    const int m0    = blockIdx.x * 64;
    const int split = blockIdx.y;
    const int batch = blockIdx.x >> 4;

    // x loader: thread covers row lr, 4 consecutive float4 at half lh
    const int lr = tid >> 1;           // 0..63
    const int lh = tid & 1;            // 0..1
    const float4* xg = reinterpret_cast<const float4*>(x)
                     + (size_t)(m0 + lr) * (DIN / 4) + lh * 4;

    const int wid  = tid >> 5;
    const int lane = tid & 31;
    const int wm = (wid & 1) * 32;     // 0 / 32
    const int wn = (wid >> 1) * 32;    // 0 / 32
    const int g = lane >> 2;
    const int t = lane & 3;

    const uint4* __restrict__ wb = g_wdp + (size_t)batch * (80 * 8 * 32);
    const int n8b = wn >> 3;           // 0 or 4

    float acc[2][4][4];
    #pragma unroll
    for (int mi = 0; mi < 2; mi++)
        #pragma unroll
        for (int ni = 0; ni < 4; ni++)
            #pragma unroll
            for (int j = 0; j < 4; j++) acc[mi][ni][j] = 0.f;

    const int kt0   = split * KT_PER_SPLIT;
    const int ktend = kt0 + KT_PER_SPLIT;

    float4 ra[4];
    #pragma unroll
    for (int j = 0; j < 4; j++) ra[j] = xg[kt0 * 8 + j];

    for (int kt = kt0; kt < ktend; ++kt) {
        const int p = kt & 1;

        // B fragments for this K-tile: k16 = 2kt, 2kt+1 ; n8 = n8b..n8b+3
        uint4 bu[2][4];
        #pragma unroll
        for (int j = 0; j < 2; j++)
            #pragma unroll
            for (int ni = 0; ni < 4; ni++)
                bu[j][ni] = wb[(((2 * kt + j) * 8 + n8b + ni) << 5) + lane];

        // stage A tile (tf32) into buffer p — conflict-free STS.128
        #pragma unroll
        for (int j = 0; j < 4; j++)
            *reinterpret_cast<uint4*>(&As[p][lr * 36 + lh * 16 + j * 4]) = f4totf(ra[j]);

        // prefetch next A tile
        {
            int nkt = (kt + 1 < ktend) ? (kt + 1) : kt;
            #pragma unroll
            for (int j = 0; j < 4; j++) ra[j] = xg[nkt * 8 + j];
        }
        __syncthreads();   // single barrier per kt (double buffer)

        #pragma unroll
        for (int j = 0; j < 2; j++) {
            #pragma unroll
            for (int hh = 0; hh < 2; hh++) {
                const int k8l = 2 * j + hh;
                unsigned a[2][4];
                #pragma unroll
                for (int mi = 0; mi < 2; mi++) {
                    const unsigned* pp = &As[p][(wm + mi * 16 + g) * 36 + k8l * 8 + t];
                    a[mi][0] = pp[0];
                    a[mi][1] = pp[8 * 36];
                    a[mi][2] = pp[4];
                    a[mi][3] = pp[8 * 36 + 4];
                }
                #pragma unroll
                for (int mi = 0; mi < 2; mi++)
                    #pragma unroll
                    for (int ni = 0; ni < 4; ni++) {
                        unsigned b0 = hh ? bu[j][ni].z : bu[j][ni].x;
                        unsigned b1 = hh ? bu[j][ni].w : bu[j][ni].y;
                        mma_tf32(acc[mi][ni], a[mi][0], a[mi][1], a[mi][2], a[mi][3], b0, b1);
                    }
            }
        }
    }

    // ---- epilogue: stage to smem, write partials in A-fragment order ----
    __syncthreads();
    float* s = reinterpret_cast<float*>(As);   // 64*68 = 4352 <= 4608 words
    #pragma unroll
    for (int mi = 0; mi < 2; mi++)
        #pragma unroll
        for (int ni = 0; ni < 4; ni++) {
            int row = wm + mi * 16 + g;
            int col = wn + ni * 8 + 2 * t;
            *reinterpret_cast<float2*>(&s[row * 68 + col]) =
                make_float2(acc[mi][ni][0], acc[mi][ni][1]);
            *reinterpret_cast<float2*>(&s[(row + 8) * 68 + col]) =
                make_float2(acc[mi][ni][2], acc[mi][ni][3]);
        }
    __syncthreads();

    float4* dst = g_hp4 + (size_t)split * HQ_N + (size_t)(m0 >> 4) * 256;
    #pragma unroll
    for (int jj = 0; jj < 8; jj++) {
        int idx = tid + jj * 128;              // 0..1023 = ml*256 + k8*32 + lane
        int ln  = idx & 31;
        int k8  = (idx >> 5) & 7;
        int ml  = idx >> 8;
        int gg = ln >> 2, tt = ln & 3;
        const float* r0 = &s[(ml * 16 + gg) * 68 + k8 * 8 + tt];
        const float* r1 = r0 + 8 * 68;
        dst[idx] = make_float4(r0[0], r1[0], r0[4], r1[4]);
    }
}

// ---------------------------------------------------------------------------
// Reduce: g_hq = cvt_tf32( sum over splits of g_hp4 ). Elementwise, coalesced.
// ---------------------------------------------------------------------------
__global__ __launch_bounds__(256) void lora_reduce() {
    int i = blockIdx.x * 256 + threadIdx.x;    // < HQ_N (grid 512)
    float4 sv = g_hp4[i];
    #pragma unroll
    for (int sp = 1; sp < NSPLIT; sp++) {
        float4 v = g_hp4[(size_t)sp * HQ_N + i];
        sv.x += v.x; sv.y += v.y; sv.z += v.z; sv.w += v.w;
    }
    uint4 o;
    o.x = f2tf(sv.x); o.y = f2tf(sv.y); o.z = f2tf(sv.z); o.w = f2tf(sv.w);
    g_hq[i] = o;
}

// ---------------------------------------------------------------------------
// GEMM2: out[m,o] = h[m,:] @ W_up[b]^T, K=64.
//   CTA 128m x 64n, 8 warps (4m x 2n), warp tile 32m x 32n. grid (64, 20).
//   NO operand smem: A fragments LDG from g_hq, B from g_wup (both L2-hot).
//   Direct fragment epilogue: STG.64 with full 32B-sector coverage.
// ---------------------------------------------------------------------------
__global__ __launch_bounds__(256) void lora_gemm2(float* __restrict__ out) {
    const int tid   = threadIdx.x;
    const int m0    = blockIdx.x * 128;
    const int n0    = blockIdx.y * 64;
    const int batch = blockIdx.x >> 3;

    const int wid  = tid >> 5;
    const int lane = tid & 31;
    const int wm = (wid & 3) * 32;     // 0..96
    const int wn = (wid >> 2) * 32;    // 0 / 32
    const int g = lane >> 2;
    const int t = lane & 3;

    const uint4* __restrict__ Ab = g_hq + (size_t)((m0 + wm) >> 4) * 256 + lane;
    const uint4* __restrict__ Bb = g_wup
        + ((size_t)batch * 160 + ((n0 + wn) >> 3)) * 128 + lane;

    float acc[2][4][4];
    #pragma unroll
    for (int mi = 0; mi < 2; mi++)
        #pragma unroll
        for (int ni = 0; ni < 4; ni++)
            #pragma unroll
            for (int j = 0; j < 4; j++) acc[mi][ni][j] = 0.f;

    #pragma unroll
    for (int k16 = 0; k16 < 4; k16++) {
        uint4 alo[2], ahi[2], bu[4];
        #pragma unroll
        for (int mi = 0; mi < 2; mi++) {
            alo[mi] = Ab[mi * 256 + (2 * k16) * 32];
            ahi[mi] = Ab[mi * 256 + (2 * k16 + 1) * 32];
        }
        #pragma unroll
        for (int ni = 0; ni < 4; ni++)
            bu[ni] = Bb[ni * 128 + k16 * 32];

        #pragma unroll
        for (int mi = 0; mi < 2; mi++)
            #pragma unroll
            for (int ni = 0; ni < 4; ni++) {
                mma_tf32(acc[mi][ni], alo[mi].x, alo[mi].y, alo[mi].z, alo[mi].w,
                         bu[ni].x, bu[ni].y);
                mma_tf32(acc[mi][ni], ahi[mi].x, ahi[mi].y, ahi[mi].z, ahi[mi].w,
                         bu[ni].z, bu[ni].w);
            }
    }

    // ---- direct fragment epilogue: STG.64, 100% sector coverage ----
    #pragma unroll
    for (int mi = 0; mi < 2; mi++)
        #pragma unroll
        for (int ni = 0; ni < 4; ni++) {
            int row = m0 + wm + mi * 16 + g;
            int col = n0 + wn + ni * 8 + 2 * t;
            *reinterpret_cast<float2*>(&out[(size_t)row * DOUT + col]) =
                make_float2(acc[mi][ni][0], acc[mi][ni][1]);
            *reinterpret_cast<float2*>(&out[(size_t)(row + 8) * DOUT + col]) =
                make_float2(acc[mi][ni][2], acc[mi][ni][3]);
        }
}

// ---------------------------------------------------------------------------
extern "C" void kernel_launch(void* const* d_in, const int* in_sizes, int n_in,
                              void* d_out, int out_size) {
    const float* x     = (const float*)d_in[0];
    const float* embed = (const float*)d_in[1];
    if (n_in >= 2 && in_sizes[0] == NB * EMB_STRIDE) {
        x     = (const float*)d_in[1];
        embed = (const float*)d_in[0];
    }
    float* out = (float*)d_out;

    lora_prepack<<<(WDP_N + WUP_N) / 256, 256>>>(embed);
    lora_gemm1<<<dim3(128, NSPLIT), 128>>>(x);
    lora_reduce<<<HQ_N / 256, 256>>>();
    lora_gemm2<<<dim3(64, 20), 256>>>(out);
}

// round 10
// speedup vs baseline: 2.3065x; 1.0878x over previous
#include <cuda_runtime.h>
#include <cstdint>
#include <cstddef>

// Problem constants
#define NB    8
#define SS    1024
#define DIN   1280
#define RNK   64
#define DOUT  1280
#define MTOT  (NB * SS)                  // 8192
#define DOWN_SIZE (RNK * DIN)            // 81920
#define UP_SIZE   (DOUT * RNK)           // 81920
#define EMB_STRIDE (DOWN_SIZE + UP_SIZE) // 163840

#define NSPLIT 8                         // K split for GEMM1 (chunks of 160)

#define M16   (MTOT / 16)                // 512 m16-blocks
#define HQ_N  (M16 * 8 * 32)             // 131072 uint4 slots (h fragments)
#define WDP_N (NB * 80 * 8 * 32)         // 163840 uint4 (W_down fragments)
#define WUP_N (NB * 160 * 4 * 32)        // 163840 uint4 (W_up fragments)

// Device scratch (static — no allocation)
__device__ float4 g_hp4[NSPLIT * HQ_N];  // split-K partials, fragment order, fp32
__device__ uint4  g_hq[HQ_N];            // reduced h, tf32, A-fragment packed
__device__ uint4  g_wdp[WDP_N];          // W_down, tf32, B-fragment packed
__device__ uint4  g_wup[WUP_N];          // W_up,   tf32, B-fragment packed

__device__ __forceinline__ unsigned f2tf(float f) {
    unsigned u;
    asm("cvt.rna.tf32.f32 %0, %1;" : "=r"(u) : "f"(f));
    return u;
}

__device__ __forceinline__ uint4 f4totf(float4 v) {
    uint4 u;
    u.x = f2tf(v.x); u.y = f2tf(v.y); u.z = f2tf(v.z); u.w = f2tf(v.w);
    return u;
}

__device__ __forceinline__ void mma_tf32(float c[4],
                                         unsigned a0, unsigned a1, unsigned a2, unsigned a3,
                                         unsigned b0, unsigned b1) {
    asm volatile(
        "mma.sync.aligned.m16n8k8.row.col.f32.tf32.tf32.f32 "
        "{%0,%1,%2,%3}, {%4,%5,%6,%7}, {%8,%9}, {%0,%1,%2,%3};"
        : "+f"(c[0]), "+f"(c[1]), "+f"(c[2]), "+f"(c[3])
        : "r"(a0), "r"(a1), "r"(a2), "r"(a3), "r"(b0), "r"(b1));
}

// ---------------------------------------------------------------------------
// Prepack: embed -> tf32 fragment-packed W_down / W_up.
//   B-fragment (m16n8k8, col-major B): lane(g,t) holds (k=t,n=g),(k=t+4,n=g);
//   two k8 steps packed per uint4: {b(k8e)0, b(k8e)1, b(k8o)0, b(k8o)1}.
//   g_wdp index: ((b*80 + k16)*8 + n8)*32 + lane      (k over d_in: 80 k16)
//   g_wup index: ((b*160 + n8)*4 + k16)*32 + lane     (k over rank: 4 k16)
// ---------------------------------------------------------------------------
__global__ __launch_bounds__(256) void lora_prepack(const float* __restrict__ embed) {
    int i = blockIdx.x * 256 + threadIdx.x;
    int lane = i & 31;
    int g = lane >> 2, t = lane & 3;
    if (i < WDP_N) {
        int r = i >> 5;
        int n8  = r & 7;  r >>= 3;
        int k16 = r % 80;
        int b   = r / 80;
        const float* W = embed + (size_t)b * EMB_STRIDE
                       + (size_t)(n8 * 8 + g) * DIN + k16 * 16;
        uint4 o;
        o.x = f2tf(W[t]); o.y = f2tf(W[t + 4]);
        o.z = f2tf(W[8 + t]); o.w = f2tf(W[12 + t]);
        g_wdp[i] = o;
    } else {
        int j = i - WDP_N;
        int r = j >> 5;
        int k16 = r & 3;  r >>= 2;
        int n8  = r % 160;
        int b   = r / 160;
        const float* W = embed + (size_t)b * EMB_STRIDE + DOWN_SIZE
                       + (size_t)(n8 * 8 + g) * RNK + k16 * 16;
        uint4 o;
        o.x = f2tf(W[t]); o.y = f2tf(W[t + 4]);
        o.z = f2tf(W[8 + t]); o.w = f2tf(W[12 + t]);
        g_wup[j] = o;
    }
}

// ---------------------------------------------------------------------------
// GEMM1 (split-K=8): partial h[m,r] over one K chunk of 160.
//   grid (128, 8), block 128 (4 warps as 2m x 2n, warp tile 32m x 32n).
//   Single-stage smem: whole 64m x 160k x-chunk staged ONCE (20 LDG.128 per
//   thread, MLP=20), one syncthreads, then a barrier-free MMA stream.
//   B (W_down): fragment LDG from g_wdp (L2-hot).
//   Epilogue: stage to smem, emit partials in A-fragment order (fp32).
// ---------------------------------------------------------------------------
#define G1_STRIDE 164   // words per row: 160 + 4 pad (164 % 32 == 4 -> conflict-free)

__global__ __launch_bounds__(128) void lora_gemm1(const float* __restrict__ x) {
    __shared__ unsigned As[64 * G1_STRIDE];   // 41,984 B

    const int tid   = threadIdx.x;
    const int m0    = blockIdx.x * 64;
    const int split = blockIdx.y;
    const int batch = blockIdx.x >> 4;

    // ---- stage the full K-chunk: thread = (row lr, half lh) ----
    const int lr = tid >> 1;           // 0..63
    const int lh = tid & 1;            // 0..1
    {
        const float4* xg = reinterpret_cast<const float4*>(x)
                         + (size_t)(m0 + lr) * (DIN / 4) + split * 40 + lh * 4;
        #pragma unroll
        for (int kt = 0; kt < 5; kt++)
            #pragma unroll
            for (int j = 0; j < 4; j++)
                *reinterpret_cast<uint4*>(&As[lr * G1_STRIDE + kt * 32 + lh * 16 + j * 4]) =
                    f4totf(xg[kt * 8 + j]);
    }

    const int wid  = tid >> 5;
    const int lane = tid & 31;
    const int wm = (wid & 1) * 32;     // 0 / 32
    const int wn = (wid >> 1) * 32;    // 0 / 32
    const int g = lane >> 2;
    const int t = lane & 3;

    const uint4* __restrict__ wb = g_wdp + (size_t)batch * (80 * 8 * 32);
    const int n8b = wn >> 3;           // 0 or 4

    float acc[2][4][4];
    #pragma unroll
    for (int mi = 0; mi < 2; mi++)
        #pragma unroll
        for (int ni = 0; ni < 4; ni++)
            #pragma unroll
            for (int j = 0; j < 4; j++) acc[mi][ni][j] = 0.f;

    __syncthreads();   // the ONLY pre-mainloop barrier

    #pragma unroll
    for (int kt = 0; kt < 5; kt++) {
        // B fragments: global k16 = split*10 + kt*2 + j ; n8 = n8b..n8b+3
        uint4 bu[2][4];
        #pragma unroll
        for (int j = 0; j < 2; j++)
            #pragma unroll
            for (int ni = 0; ni < 4; ni++)
                bu[j][ni] = wb[(((split * 10 + 2 * kt + j) * 8 + n8b + ni) << 5) + lane];

        #pragma unroll
        for (int j = 0; j < 2; j++) {
            #pragma unroll
            for (int hh = 0; hh < 2; hh++) {
                const int k8l = 2 * j + hh;
                unsigned a[2][4];
                #pragma unroll
                for (int mi = 0; mi < 2; mi++) {
                    const unsigned* pp =
                        &As[(wm + mi * 16 + g) * G1_STRIDE + kt * 32 + k8l * 8 + t];
                    a[mi][0] = pp[0];
                    a[mi][1] = pp[8 * G1_STRIDE];
                    a[mi][2] = pp[4];
                    a[mi][3] = pp[8 * G1_STRIDE + 4];
                }
                #pragma unroll
                for (int mi = 0; mi < 2; mi++)
                    #pragma unroll
                    for (int ni = 0; ni < 4; ni++) {
                        unsigned b0 = hh ? bu[j][ni].z : bu[j][ni].x;
                        unsigned b1 = hh ? bu[j][ni].w : bu[j][ni].y;
                        mma_tf32(acc[mi][ni], a[mi][0], a[mi][1], a[mi][2], a[mi][3], b0, b1);
                    }
            }
        }
    }

    // ---- epilogue: stage to smem, write partials in A-fragment order ----
    __syncthreads();
    float* s = reinterpret_cast<float*>(As);   // [64][68] floats
    #pragma unroll
    for (int mi = 0; mi < 2; mi++)
        #pragma unroll
        for (int ni = 0; ni < 4; ni++) {
            int row = wm + mi * 16 + g;
            int col = wn + ni * 8 + 2 * t;
            *reinterpret_cast<float2*>(&s[row * 68 + col]) =
                make_float2(acc[mi][ni][0], acc[mi][ni][1]);
            *reinterpret_cast<float2*>(&s[(row + 8) * 68 + col]) =
                make_float2(acc[mi][ni][2], acc[mi][ni][3]);
        }
    __syncthreads();

    float4* dst = g_hp4 + (size_t)split * HQ_N + (size_t)(m0 >> 4) * 256;
    #pragma unroll
    for (int jj = 0; jj < 8; jj++) {
        int idx = tid + jj * 128;              // 0..1023 = ml*256 + k8*32 + lane
        int ln  = idx & 31;
        int k8  = (idx >> 5) & 7;
        int ml  = idx >> 8;
        int gg = ln >> 2, tt = ln & 3;
        const float* r0 = &s[(ml * 16 + gg) * 68 + k8 * 8 + tt];
        const float* r1 = r0 + 8 * 68;
        dst[idx] = make_float4(r0[0], r1[0], r0[4], r1[4]);
    }
}

// ---------------------------------------------------------------------------
// Reduce: g_hq = cvt_tf32( sum over splits of g_hp4 ). Elementwise, coalesced.
// ---------------------------------------------------------------------------
__global__ __launch_bounds__(256) void lora_reduce() {
    int i = blockIdx.x * 256 + threadIdx.x;    // < HQ_N (grid 512)
    float4 sv = g_hp4[i];
    #pragma unroll
    for (int sp = 1; sp < NSPLIT; sp++) {
        float4 v = g_hp4[(size_t)sp * HQ_N + i];
        sv.x += v.x; sv.y += v.y; sv.z += v.z; sv.w += v.w;
    }
    uint4 o;
    o.x = f2tf(sv.x); o.y = f2tf(sv.y); o.z = f2tf(sv.z); o.w = f2tf(sv.w);
    g_hq[i] = o;
}

// ---------------------------------------------------------------------------
// GEMM2: out[m,o] = h[m,:] @ W_up[b]^T, K=64.
//   CTA 64m x 64n, block 128 (4 warps as 2m x 2n, warp tile 32m x 32n).
//   grid (128, 20) = 2560 CTAs -> ~7 resident CTAs/SM for latency hiding.
//   NO operand smem: A fragments LDG from g_hq, B from g_wup (both L2-hot).
//   Direct fragment epilogue: STG.64 with full 32B-sector coverage.
// ---------------------------------------------------------------------------
__global__ __launch_bounds__(128) void lora_gemm2(float* __restrict__ out) {
    const int tid   = threadIdx.x;
    const int m0    = blockIdx.x * 64;
    const int n0    = blockIdx.y * 64;
    const int batch = blockIdx.x >> 4;

    const int wid  = tid >> 5;
    const int lane = tid & 31;
    const int wm = (wid & 1) * 32;     // 0 / 32
    const int wn = (wid >> 1) * 32;    // 0 / 32
    const int g = lane >> 2;
    const int t = lane & 3;

    const uint4* __restrict__ Ab = g_hq + (size_t)((m0 + wm) >> 4) * 256 + lane;
    const uint4* __restrict__ Bb = g_wup
        + ((size_t)batch * 160 + ((n0 + wn) >> 3)) * 128 + lane;

    float acc[2][4][4];
    #pragma unroll
    for (int mi = 0; mi < 2; mi++)
        #pragma unroll
        for (int ni = 0; ni < 4; ni++)
            #pragma unroll
            for (int j = 0; j < 4; j++) acc[mi][ni][j] = 0.f;

    #pragma unroll
    for (int k16 = 0; k16 < 4; k16++) {
        uint4 alo[2], ahi[2], bu[4];
        #pragma unroll
        for (int mi = 0; mi < 2; mi++) {
            alo[mi] = Ab[mi * 256 + (2 * k16) * 32];
            ahi[mi] = Ab[mi * 256 + (2 * k16 + 1) * 32];
        }
        #pragma unroll
        for (int ni = 0; ni < 4; ni++)
            bu[ni] = Bb[ni * 128 + k16 * 32];

        #pragma unroll
        for (int mi = 0; mi < 2; mi++)
            #pragma unroll
            for (int ni = 0; ni < 4; ni++) {
                mma_tf32(acc[mi][ni], alo[mi].x, alo[mi].y, alo[mi].z, alo[mi].w,
                         bu[ni].x, bu[ni].y);
                mma_tf32(acc[mi][ni], ahi[mi].x, ahi[mi].y, ahi[mi].z, ahi[mi].w,
                         bu[ni].z, bu[ni].w);
            }
    }

    // ---- direct fragment epilogue: STG.64, 100% sector coverage ----
    #pragma unroll
    for (int mi = 0; mi < 2; mi++)
        #pragma unroll
        for (int ni = 0; ni < 4; ni++) {
            int row = m0 + wm + mi * 16 + g;
            int col = n0 + wn + ni * 8 + 2 * t;
            *reinterpret_cast<float2*>(&out[(size_t)row * DOUT + col]) =
                make_float2(acc[mi][ni][0], acc[mi][ni][1]);
            *reinterpret_cast<float2*>(&out[(size_t)(row + 8) * DOUT + col]) =
                make_float2(acc[mi][ni][2], acc[mi][ni][3]);
        }
}

// ---------------------------------------------------------------------------
extern "C" void kernel_launch(void* const* d_in, const int* in_sizes, int n_in,
                              void* d_out, int out_size) {
    const float* x     = (const float*)d_in[0];
    const float* embed = (const float*)d_in[1];
    if (n_in >= 2 && in_sizes[0] == NB * EMB_STRIDE) {
        x     = (const float*)d_in[1];
        embed = (const float*)d_in[0];
    }
    float* out = (float*)d_out;

    lora_prepack<<<(WDP_N + WUP_N) / 256, 256>>>(embed);
    lora_gemm1<<<dim3(128, NSPLIT), 128>>>(x);
    lora_reduce<<<HQ_N / 256, 256>>>();
    lora_gemm2<<<dim3(128, 20), 128>>>(out);
}